// round 1
// baseline (speedup 1.0000x reference)
#include <cuda_runtime.h>
#include <math.h>
#include <stdint.h>

#define BB    2
#define NS    4
#define TT    2048
#define DD    1024
#define EE    16
#define NDIM  4096           // NS*DD
#define DFFN  1656
#define BT    (BB*TT)        // 4096 tokens
#define CAP   BT             // per-expert row capacity
#define EPS_F 1.1920929e-7f

// ---------------- device scratch (allocation-free rule: __device__ globals) ----
__device__ float g_srms[BT];
__device__ int   g_row [BT*EE];
__device__ float g_gatev[BT*EE];
__device__ int   g_cnt [EE];
__device__ float g_Hpost[(size_t)EE*CAP*NS];
__device__ float g_Hres [(size_t)EE*CAP*NS*NS];
__device__ float g_HN [(size_t)EE*CAP*DD];     // 256 MB
__device__ float g_T1 [(size_t)EE*CAP*DD];     // 256 MB
__device__ float g_GS [(size_t)EE*CAP*DD];     // 256 MB
__device__ float g_P  [(size_t)EE*CAP*DFFN];   // 434 MB
__device__ float g_OUT[(size_t)EE*CAP*DD];     // 256 MB

#define ID_HN 0
#define ID_T1 1
#define ID_GS 2
#define ID_P  3
#define ID_OUT 4

__device__ __forceinline__ float* buf_ptr(int id) {
    switch (id) {
        case ID_HN: return g_HN;
        case ID_T1: return g_T1;
        case ID_GS: return g_GS;
        case ID_P:  return g_P;
        default:    return g_OUT;
    }
}
__device__ __forceinline__ int buf_ld(int id) { return (id == ID_P) ? DFFN : DD; }

// ---------------- kernel 0: zero per-expert counters ---------------------------
__global__ void k_zero() {
    if (threadIdx.x < EE) g_cnt[threadIdx.x] = 0;
}

// ---------------- kernel 1: router logits, softmax-topk gate, token RMS --------
__global__ void __launch_bounds__(256) k_gate(const float* __restrict__ stream,
                                              const float* __restrict__ router_w,
                                              float* __restrict__ out_gate)
{
    int token = blockIdx.x;
    int b = token / TT, t = token % TT;
    int tid = threadIdx.x;
    __shared__ float route[DD];
    __shared__ float red[256];
    __shared__ float logit[EE];

    const float* sp0 = stream + ((size_t)b * NS * TT + t) * DD;  // stream[b,0,t,:]
    float ss = 0.f;
    for (int dd = tid; dd < DD; dd += 256) {
        float v0 = sp0[dd];
        float v1 = sp0[(size_t)TT * DD + dd];
        float v2 = sp0[2 * (size_t)TT * DD + dd];
        float v3 = sp0[3 * (size_t)TT * DD + dd];
        ss += v0 * v0 + v1 * v1 + v2 * v2 + v3 * v3;
        route[dd] = 0.25f * (v0 + v1 + v2 + v3);
    }
    red[tid] = ss;
    __syncthreads();
    for (int s = 128; s > 0; s >>= 1) {
        if (tid < s) red[tid] += red[tid + s];
        __syncthreads();
    }
    if (tid == 0) g_srms[token] = rsqrtf(red[0] / (float)NDIM + EPS_F);

    int warp = tid >> 5, lane = tid & 31;
    for (int e = warp; e < EE; e += 8) {
        const float* rw = router_w + (size_t)e * DD;
        float acc = 0.f;
        for (int dd = lane; dd < DD; dd += 32) acc += route[dd] * rw[dd];
        #pragma unroll
        for (int o = 16; o > 0; o >>= 1) acc += __shfl_down_sync(0xffffffffu, acc, o);
        if (lane == 0) logit[e] = acc;
    }
    __syncthreads();

    if (tid == 0) {
        float p[EE];
        float mx = -1e30f;
        #pragma unroll
        for (int e = 0; e < EE; e++) mx = fmaxf(mx, logit[e]);
        float sum = 0.f;
        #pragma unroll
        for (int e = 0; e < EE; e++) { p[e] = expf(logit[e] - mx); sum += p[e]; }
        float inv = 1.f / sum;
        #pragma unroll
        for (int e = 0; e < EE; e++) p[e] *= inv;

        // stable descending insertion sort (matches jnp.argsort(-probs))
        int ord[EE];
        #pragma unroll
        for (int e = 0; e < EE; e++) ord[e] = e;
        for (int i = 1; i < EE; i++) {
            int oi = ord[i]; float pi = p[oi];
            int j = i - 1;
            while (j >= 0 && p[ord[j]] < pi) { ord[j + 1] = ord[j]; j--; }
            ord[j + 1] = oi;
        }
        float cum = 0.f;
        float gate[EE];
        #pragma unroll
        for (int e = 0; e < EE; e++) gate[e] = 0.f;
        for (int r = 0; r < EE; r++) {
            int e = ord[r];
            bool sel = (r == 0) || (cum < 0.8f && r < 4);
            if (sel) gate[e] = p[e];
            cum += p[e];
        }
        for (int e = 0; e < EE; e++) {
            float g = gate[e];
            out_gate[(size_t)token * EE + e] = g;
            g_gatev[token * EE + e] = g;
            int row = -1;
            if (g > 0.f) row = atomicAdd(&g_cnt[e], 1);
            g_row[token * EE + e] = row;
        }
    }
}

// ---------------- kernel 2: per-(token,expert) H_pre/H_post/H_res + hn ---------
__global__ void __launch_bounds__(128) k_mix(const float* __restrict__ stream,
                                             const float* __restrict__ mhc_norm_w,
                                             const float* __restrict__ phi_pre_w,
                                             const float* __restrict__ phi_post_w,
                                             const float* __restrict__ phi_res_w,
                                             const float* __restrict__ b_pre,
                                             const float* __restrict__ b_post,
                                             const float* __restrict__ b_res,
                                             const float* __restrict__ alpha_pre,
                                             const float* __restrict__ alpha_post,
                                             const float* __restrict__ alpha_res,
                                             const float* __restrict__ sw_norm_w)
{
    int token = blockIdx.x;
    int e = blockIdx.y;
    int row = g_row[token * EE + e];
    if (row < 0) return;
    int tid = threadIdx.x;
    int b = token / TT, t = token % TT;

    __shared__ float xsh[NDIM];
    __shared__ float hsh[DD];
    __shared__ float dsh[24];
    __shared__ float hpre[NS];
    __shared__ float red2[4];

    float s = g_srms[token];
    const float* sp0 = stream + ((size_t)b * NS * TT + t) * DD;
    const float* nw = mhc_norm_w + (size_t)e * NDIM;
    for (int j = tid; j < NDIM; j += 128) {
        int i = j >> 10, dd = j & 1023;
        xsh[j] = sp0[(size_t)i * TT * DD + dd] * s * nw[j];
    }
    __syncthreads();

    int warp = tid >> 5, lane = tid & 31;
    for (int dIdx = warp; dIdx < 24; dIdx += 4) {
        const float* wrow;
        if (dIdx < 4)       wrow = phi_pre_w  + ((size_t)e * NS + dIdx) * NDIM;
        else if (dIdx < 8)  wrow = phi_post_w + ((size_t)e * NS + (dIdx - 4)) * NDIM;
        else                wrow = phi_res_w  + ((size_t)e * NS * NS + (dIdx - 8)) * NDIM;
        float acc = 0.f;
        for (int j = lane; j < NDIM; j += 32) acc += xsh[j] * wrow[j];
        #pragma unroll
        for (int o = 16; o > 0; o >>= 1) acc += __shfl_down_sync(0xffffffffu, acc, o);
        if (lane == 0) dsh[dIdx] = acc;
    }
    __syncthreads();

    if (tid == 0) {
        size_t slot = (size_t)e * CAP + row;
        float ap = alpha_pre[e], ao = alpha_post[e], ar = alpha_res[e];
        #pragma unroll
        for (int i = 0; i < NS; i++)
            hpre[i] = 1.f / (1.f + expf(-(ap * dsh[i] + b_pre[e * NS + i])));
        #pragma unroll
        for (int i = 0; i < NS; i++)
            g_Hpost[slot * NS + i] = 2.f / (1.f + expf(-(ao * dsh[4 + i] + b_post[e * NS + i])));
        float M[16];
        #pragma unroll
        for (int k = 0; k < 16; k++) M[k] = expf(ar * dsh[8 + k] + b_res[e * 16 + k]);
        for (int it = 0; it < 6; it++) {
            #pragma unroll
            for (int i = 0; i < 4; i++) {
                float rs = M[i*4] + M[i*4+1] + M[i*4+2] + M[i*4+3];
                float ir = 1.f / rs;
                M[i*4] *= ir; M[i*4+1] *= ir; M[i*4+2] *= ir; M[i*4+3] *= ir;
            }
            #pragma unroll
            for (int j = 0; j < 4; j++) {
                float cs = M[j] + M[4+j] + M[8+j] + M[12+j];
                float ic = 1.f / cs;
                M[j] *= ic; M[4+j] *= ic; M[8+j] *= ic; M[12+j] *= ic;
            }
        }
        #pragma unroll
        for (int k = 0; k < 16; k++) g_Hres[slot * 16 + k] = M[k];
    }
    __syncthreads();

    // h = sum_i Hpre[i] * stream[b,i,t,:], then hn = rms(h) * sw_norm_w
    float hq = 0.f;
    for (int dd = tid; dd < DD; dd += 128) {
        float h = hpre[0] * sp0[dd]
                + hpre[1] * sp0[(size_t)TT * DD + dd]
                + hpre[2] * sp0[2 * (size_t)TT * DD + dd]
                + hpre[3] * sp0[3 * (size_t)TT * DD + dd];
        hsh[dd] = h;
        hq += h * h;
    }
    #pragma unroll
    for (int o = 16; o > 0; o >>= 1) hq += __shfl_down_sync(0xffffffffu, hq, o);
    if (lane == 0) red2[warp] = hq;
    __syncthreads();
    if (tid == 0) red2[0] = rsqrtf((red2[0] + red2[1] + red2[2] + red2[3]) / (float)DD + EPS_F);
    __syncthreads();
    float sh = red2[0];
    const float* snw = sw_norm_w + (size_t)e * DD;
    float* hn = g_HN + ((size_t)e * CAP + row) * DD;
    for (int dd = tid; dd < DD; dd += 128) hn[dd] = hsh[dd] * sh * snw[dd];
}

// ---------------- kernel 3: batched-per-expert GEMM, fused epilogues -----------
// C[m,n] = epilogue( sum_k A[m,k] * W[n,k] )
// MODE 0: silu   MODE 1: sigmoid   MODE 2: multiply by Aux[m,n]
template <int MODE>
__global__ void __launch_bounds__(256) k_gemm(int aId, const float* __restrict__ Wbase,
                                              int cId, int auxId, int N, int K)
{
    int e = blockIdx.z;
    int cnt = g_cnt[e];
    int m0 = blockIdx.x * 128;
    if (m0 >= cnt) return;
    int n0 = blockIdx.y * 64;

    int lda = buf_ld(aId), ldc = buf_ld(cId);
    const float* A = buf_ptr(aId) + (size_t)e * CAP * lda;
    const float* W = Wbase + (size_t)e * N * K;
    float* C = buf_ptr(cId) + (size_t)e * CAP * ldc;

    __shared__ float As[16][132];
    __shared__ float Bs[16][68];

    int tid = threadIdx.x;
    int ty = tid >> 4, tx = tid & 15;
    float acc[8][4];
    #pragma unroll
    for (int i = 0; i < 8; i++)
        #pragma unroll
        for (int j = 0; j < 4; j++) acc[i][j] = 0.f;

    for (int k0 = 0; k0 < K; k0 += 16) {
        #pragma unroll
        for (int s = 0; s < 8; s++) {
            int l = tid + s * 256;
            int r = l >> 4, c = l & 15;
            int m = m0 + r, kk = k0 + c;
            As[c][r] = (m < cnt && kk < K) ? A[(size_t)m * lda + kk] : 0.f;
        }
        #pragma unroll
        for (int s = 0; s < 4; s++) {
            int l = tid + s * 256;
            int n = l >> 4, c = l & 15;
            int nn = n0 + n, kk = k0 + c;
            Bs[c][n] = (nn < N && kk < K) ? W[(size_t)nn * K + kk] : 0.f;
        }
        __syncthreads();
        #pragma unroll
        for (int k = 0; k < 16; k++) {
            float a[8], bb[4];
            #pragma unroll
            for (int i = 0; i < 8; i++) a[i] = As[k][ty * 8 + i];
            #pragma unroll
            for (int j = 0; j < 4; j++) bb[j] = Bs[k][tx * 4 + j];
            #pragma unroll
            for (int i = 0; i < 8; i++)
                #pragma unroll
                for (int j = 0; j < 4; j++) acc[i][j] = fmaf(a[i], bb[j], acc[i][j]);
        }
        __syncthreads();
    }

    const float* Aux = nullptr;
    int ldaux = ldc;
    if (MODE == 2) {
        ldaux = buf_ld(auxId);
        Aux = buf_ptr(auxId) + (size_t)e * CAP * ldaux;
    }
    #pragma unroll
    for (int i = 0; i < 8; i++) {
        int m = m0 + ty * 8 + i;
        if (m >= cnt) continue;
        #pragma unroll
        for (int j = 0; j < 4; j++) {
            int n = n0 + tx * 4 + j;
            if (n >= N) continue;
            float v = acc[i][j];
            if (MODE == 0)      v = v / (1.f + expf(-v));         // silu
            else if (MODE == 1) v = 1.f / (1.f + expf(-v));       // sigmoid
            else                v = v * Aux[(size_t)m * ldaux + n];
            C[(size_t)m * ldc + n] = v;
        }
    }
}

// ---------------- kernel 4: combine res + post, write stream_update ------------
__global__ void __launch_bounds__(128) k_out(const float* __restrict__ stream,
                                             float* __restrict__ outp)
{
    int token = blockIdx.x;
    int b = token / TT, t = token % TT;
    int tid = threadIdx.x;
    const float* sp0 = stream + ((size_t)b * NS * TT + t) * DD;

    float st[4][8], acc[4][8];
    #pragma unroll
    for (int i = 0; i < 4; i++)
        #pragma unroll
        for (int j = 0; j < 8; j++) {
            st[i][j] = sp0[(size_t)i * TT * DD + tid + j * 128];
            acc[i][j] = 0.f;
        }

    for (int e = 0; e < EE; e++) {
        int row = g_row[token * EE + e];
        if (row < 0) continue;
        float g = g_gatev[token * EE + e];
        size_t slot = (size_t)e * CAP + row;
        float Hr[16], Hp[4];
        #pragma unroll
        for (int k = 0; k < 16; k++) Hr[k] = g_Hres[slot * 16 + k];
        #pragma unroll
        for (int i = 0; i < 4; i++) Hp[i] = g_Hpost[slot * 4 + i];
        const float* o = g_OUT + slot * DD;
        #pragma unroll
        for (int j = 0; j < 8; j++) {
            float ov = o[tid + j * 128];
            #pragma unroll
            for (int i = 0; i < 4; i++) {
                float r = Hr[i*4+0] * st[0][j] + Hr[i*4+1] * st[1][j]
                        + Hr[i*4+2] * st[2][j] + Hr[i*4+3] * st[3][j];
                acc[i][j] += g * (r + Hp[i] * ov);
            }
        }
    }
    #pragma unroll
    for (int i = 0; i < 4; i++)
        #pragma unroll
        for (int j = 0; j < 8; j++)
            outp[((size_t)(b * NS + i) * TT + t) * DD + tid + j * 128] = acc[i][j];
}

// ---------------- launch -------------------------------------------------------
extern "C" void kernel_launch(void* const* d_in, const int* in_sizes, int n_in,
                              void* d_out, int out_size)
{
    (void)in_sizes; (void)n_in; (void)out_size;
    const float* stream     = (const float*)d_in[0];
    const float* router_w   = (const float*)d_in[1];
    const float* mhc_norm_w = (const float*)d_in[2];
    const float* phi_pre_w  = (const float*)d_in[3];
    const float* phi_post_w = (const float*)d_in[4];
    const float* phi_res_w  = (const float*)d_in[5];
    const float* b_pre      = (const float*)d_in[6];
    const float* b_post     = (const float*)d_in[7];
    const float* b_res      = (const float*)d_in[8];
    const float* alpha_pre  = (const float*)d_in[9];
    const float* alpha_post = (const float*)d_in[10];
    const float* alpha_res  = (const float*)d_in[11];
    const float* sw_norm_w  = (const float*)d_in[12];
    const float* wd_w       = (const float*)d_in[13];
    const float* wu_w       = (const float*)d_in[14];
    const float* gate_w     = (const float*)d_in[15];
    const float* up_w       = (const float*)d_in[16];
    const float* down_w     = (const float*)d_in[17];

    float* outp = (float*)d_out;
    float* out_gate = outp + (size_t)BB * NS * TT * DD;

    k_zero<<<1, 32>>>();
    k_gate<<<BT, 256>>>(stream, router_w, out_gate);
    k_mix<<<dim3(BT, EE), 128>>>(stream, mhc_norm_w, phi_pre_w, phi_post_w, phi_res_w,
                                 b_pre, b_post, b_res, alpha_pre, alpha_post, alpha_res,
                                 sw_norm_w);

    dim3 gD(CAP / 128, (DD + 63) / 64, EE);     // N = 1024
    dim3 gF(CAP / 128, (DFFN + 63) / 64, EE);   // N = 1656

    // T1 = silu(HN @ wd^T)
    k_gemm<0><<<gD, 256>>>(ID_HN, wd_w, ID_T1, -1, DD, DD);
    // GS = sigmoid(T1 @ wu^T)
    k_gemm<1><<<gD, 256>>>(ID_T1, wu_w, ID_GS, -1, DD, DD);
    // P = silu(HN @ gate_w^T)
    k_gemm<0><<<gF, 256>>>(ID_HN, gate_w, ID_P, -1, DFFN, DD);
    // P = (HN @ up_w^T) * P
    k_gemm<2><<<gF, 256>>>(ID_HN, up_w, ID_P, ID_P, DFFN, DD);
    // OUT = (P @ down_w^T) * GS
    k_gemm<2><<<gD, 256>>>(ID_P, down_w, ID_OUT, ID_GS, DD, DFFN);

    k_out<<<BT, 128>>>(stream, outp);
}

// round 2
// speedup vs baseline: 3.6761x; 3.6761x over previous
#include <cuda_runtime.h>
#include <math.h>
#include <stdint.h>

#define BB    2
#define NS    4
#define TT    2048
#define DD    1024
#define EE    16
#define NDIM  4096
#define DFFN  1656
#define LDP   1664          // DFFN padded to 32 multiple
#define BT    (BB*TT)       // 4096 tokens
#define CAP   BT
#define EPS_F 1.1920929e-7f

// ---------------- device scratch --------------------------------------------
__device__ float g_srms[BT];
__device__ int   g_row [BT*EE];
__device__ float g_gatev[BT*EE];
__device__ int   g_tok [EE*CAP];
__device__ int   g_cnt [EE];
__device__ float g_Hpost[(size_t)EE*CAP*NS];
__device__ float g_Hres [(size_t)EE*CAP*16];
__device__ float g_HN  [(size_t)EE*CAP*DD];
__device__ float g_T1  [(size_t)EE*CAP*DD];
__device__ float g_GS  [(size_t)EE*CAP*DD];
__device__ float g_P   [(size_t)EE*CAP*LDP];
__device__ float g_OUT [(size_t)EE*CAP*DD];
__device__ float g_base[(size_t)BT*NDIM];      // rms(flat stream) per token
__device__ float g_dots[(size_t)BT*384];       // 24 phi logits x 16 experts
__device__ float g_phiW[(size_t)EE*24*NDIM];   // packed phi weights * mhc_norm

#define ID_HN   0
#define ID_T1   1
#define ID_GS   2
#define ID_P    3
#define ID_OUT  4
#define ID_BASE 5
#define ID_DOTS 6

__device__ __forceinline__ float* buf_ptr(int id) {
    switch (id) {
        case ID_HN:   return g_HN;
        case ID_T1:   return g_T1;
        case ID_GS:   return g_GS;
        case ID_P:    return g_P;
        case ID_OUT:  return g_OUT;
        case ID_BASE: return g_base;
        default:      return g_dots;
    }
}
__device__ __forceinline__ int buf_ld(int id) {
    if (id == ID_P) return LDP;
    if (id == ID_BASE) return NDIM;
    if (id == ID_DOTS) return 384;
    return DD;
}

// ---------------- ptx helpers -----------------------------------------------
__device__ __forceinline__ uint32_t f2tf(float f) {
    uint32_t u;
    asm("cvt.rna.tf32.f32 %0, %1;" : "=r"(u) : "f"(f));
    return u;
}
__device__ __forceinline__ void mma8(float* c, const uint32_t* a, uint32_t b0, uint32_t b1) {
    asm volatile(
        "mma.sync.aligned.m16n8k8.row.col.f32.tf32.tf32.f32 "
        "{%0,%1,%2,%3}, {%4,%5,%6,%7}, {%8,%9}, {%0,%1,%2,%3};"
        : "+f"(c[0]), "+f"(c[1]), "+f"(c[2]), "+f"(c[3])
        : "r"(a[0]), "r"(a[1]), "r"(a[2]), "r"(a[3]), "r"(b0), "r"(b1));
}
__device__ __forceinline__ void cp16(uint32_t saddr, const void* g, bool pred) {
    int bytes = pred ? 16 : 0;
    asm volatile("cp.async.cg.shared.global [%0], [%1], 16, %2;"
                 :: "r"(saddr), "l"(g), "r"(bytes));
}
__device__ __forceinline__ void cp_commit() { asm volatile("cp.async.commit_group;"); }

// ---------------- kernel 0: zero counters -----------------------------------
__global__ void k_zero() { if (threadIdx.x < EE) g_cnt[threadIdx.x] = 0; }

// ---------------- kernel 1: router gate + token rms -------------------------
__global__ void __launch_bounds__(256) k_gate(const float* __restrict__ stream,
                                              const float* __restrict__ router_w,
                                              float* __restrict__ out_gate)
{
    int token = blockIdx.x;
    int b = token / TT, t = token % TT;
    int tid = threadIdx.x;
    __shared__ float route[DD];
    __shared__ float red[256];
    __shared__ float logit[EE];

    const float* sp0 = stream + ((size_t)b * NS * TT + t) * DD;
    float ss = 0.f;
    for (int dd = tid; dd < DD; dd += 256) {
        float v0 = sp0[dd];
        float v1 = sp0[(size_t)TT * DD + dd];
        float v2 = sp0[2 * (size_t)TT * DD + dd];
        float v3 = sp0[3 * (size_t)TT * DD + dd];
        ss += v0 * v0 + v1 * v1 + v2 * v2 + v3 * v3;
        route[dd] = 0.25f * (v0 + v1 + v2 + v3);
    }
    red[tid] = ss;
    __syncthreads();
    for (int s = 128; s > 0; s >>= 1) {
        if (tid < s) red[tid] += red[tid + s];
        __syncthreads();
    }
    if (tid == 0) g_srms[token] = rsqrtf(red[0] / (float)NDIM + EPS_F);

    int warp = tid >> 5, lane = tid & 31;
    for (int e = warp; e < EE; e += 8) {
        const float* rw = router_w + (size_t)e * DD;
        float acc = 0.f;
        for (int dd = lane; dd < DD; dd += 32) acc += route[dd] * rw[dd];
        #pragma unroll
        for (int o = 16; o > 0; o >>= 1) acc += __shfl_down_sync(0xffffffffu, acc, o);
        if (lane == 0) logit[e] = acc;
    }
    __syncthreads();

    if (tid == 0) {
        float p[EE];
        float mx = -1e30f;
        #pragma unroll
        for (int e = 0; e < EE; e++) mx = fmaxf(mx, logit[e]);
        float sum = 0.f;
        #pragma unroll
        for (int e = 0; e < EE; e++) { p[e] = expf(logit[e] - mx); sum += p[e]; }
        float inv = 1.f / sum;
        #pragma unroll
        for (int e = 0; e < EE; e++) p[e] *= inv;

        int ord[EE];
        #pragma unroll
        for (int e = 0; e < EE; e++) ord[e] = e;
        for (int i = 1; i < EE; i++) {
            int oi = ord[i]; float pi = p[oi];
            int j = i - 1;
            while (j >= 0 && p[ord[j]] < pi) { ord[j + 1] = ord[j]; j--; }
            ord[j + 1] = oi;
        }
        float cum = 0.f;
        float gate[EE];
        #pragma unroll
        for (int e = 0; e < EE; e++) gate[e] = 0.f;
        for (int r = 0; r < EE; r++) {
            int e = ord[r];
            bool sel = (r == 0) || (cum < 0.8f && r < 4);
            if (sel) gate[e] = p[e];
            cum += p[e];
        }
        for (int e = 0; e < EE; e++) {
            float g = gate[e];
            out_gate[(size_t)token * EE + e] = g;
            g_gatev[token * EE + e] = g;
            int row = -1;
            if (g > 0.f) {
                row = atomicAdd(&g_cnt[e], 1);
                g_tok[e * CAP + row] = token;
            }
            g_row[token * EE + e] = row;
        }
    }
}

// ---------------- kernel 2a: materialize base = rms(flat stream) ------------
__global__ void __launch_bounds__(256) k_base(const float* __restrict__ stream)
{
    int token = blockIdx.x;
    int b = token / TT, t = token % TT;
    float s = g_srms[token];
    const float* sp0 = stream + ((size_t)b * NS * TT + t) * DD;
    float* dst = g_base + (size_t)token * NDIM;
    for (int j = threadIdx.x; j < NDIM; j += 256) {
        int i = j >> 10, dd = j & 1023;
        dst[j] = sp0[(size_t)i * TT * DD + dd] * s;
    }
}

// ---------------- kernel 2b: pack phi weights (fold mhc_norm_w) -------------
__global__ void __launch_bounds__(256) k_pack(const float* __restrict__ mhc_norm_w,
                                              const float* __restrict__ phi_pre_w,
                                              const float* __restrict__ phi_post_w,
                                              const float* __restrict__ phi_res_w)
{
    int base = blockIdx.x * 1024;
    #pragma unroll
    for (int u = 0; u < 4; u++) {
        int idx = base + u * 256 + threadIdx.x;
        int e = idx / (24 * NDIM);
        int rem = idx - e * 24 * NDIM;
        int r = rem >> 12;
        int j = rem & 4095;
        float w;
        if (r < 4)       w = phi_pre_w [((size_t)e * 4 + r) * NDIM + j];
        else if (r < 8)  w = phi_post_w[((size_t)e * 4 + (r - 4)) * NDIM + j];
        else             w = phi_res_w [((size_t)e * 16 + (r - 8)) * NDIM + j];
        g_phiW[idx] = w * mhc_norm_w[(size_t)e * NDIM + j];
    }
}

// ---------------- kernel 3: tf32 tensor-core GEMM ---------------------------
// C[m,n] = epilogue( sum_k A[m,k] * W[n,k] )
// MODE 0: silu  1: sigmoid  2: mul by Aux[m,n]  3: raw store
template <int MODE>
__global__ void __launch_bounds__(256, 2) k_gemm(int aId, const float* __restrict__ Wbase,
                                                 int cId, int auxId, int N, int K, int Kact,
                                                 int cntOv)
{
    extern __shared__ float sm[];
    int e = blockIdx.z;
    int cnt = (cntOv >= 0) ? cntOv : g_cnt[e];
    int m0 = blockIdx.x * 128;
    if (m0 >= cnt) return;
    int n0 = blockIdx.y * 128;

    int lda = buf_ld(aId), ldc = buf_ld(cId);
    const float* A = buf_ptr(aId) + (size_t)e * CAP * lda;
    const float* W = Wbase + (size_t)e * N * Kact;
    float* C = buf_ptr(cId) + (size_t)e * CAP * ldc;

    uint32_t sbase = (uint32_t)__cvta_generic_to_shared(sm);
    int tid = threadIdx.x;
    int lane = tid & 31, warp = tid >> 5;
    int wm = warp >> 1, wn = warp & 1;
    int qr = lane >> 2, qc = lane & 3;

    float acc[2][8][4];
    #pragma unroll
    for (int mt = 0; mt < 2; mt++)
        #pragma unroll
        for (int nt = 0; nt < 8; nt++)
            #pragma unroll
            for (int q = 0; q < 4; q++) acc[mt][nt][q] = 0.f;

    int KT = K / 32;

    // issue loads for stage s, k-block kt
    auto load_stage = [&](int kt, int stg) {
        int k0 = kt * 32;
        #pragma unroll
        for (int s4 = 0; s4 < 4; s4++) {
            int f = tid + s4 * 256;
            int row = f >> 3, c4 = f & 7;
            const float* gp = A + (size_t)(m0 + row) * lda + k0 + c4 * 4;
            cp16(sbase + ((stg * 4608 + row * 36 + c4 * 4) << 2), gp, true);
        }
        #pragma unroll
        for (int s4 = 0; s4 < 4; s4++) {
            int f = tid + s4 * 256;
            int row = f >> 3, c4 = f & 7;
            int nn = n0 + row;
            int kk = k0 + c4 * 4;
            bool pred = (nn < N) && (kk < Kact);
            const float* gp = pred ? (W + (size_t)nn * Kact + kk) : W;
            cp16(sbase + ((9216 + stg * 4608 + row * 36 + c4 * 4) << 2), gp, pred);
        }
        cp_commit();
    };

    load_stage(0, 0);

    for (int kt = 0; kt < KT; kt++) {
        if (kt + 1 < KT) load_stage(kt + 1, (kt + 1) & 1);
        if (kt + 1 < KT) asm volatile("cp.async.wait_group 1;");
        else             asm volatile("cp.async.wait_group 0;");
        __syncthreads();

        int stg = kt & 1;
        const float* Asm = sm + stg * 4608;
        const float* Bsm = sm + 9216 + stg * 4608;

        #pragma unroll
        for (int ks = 0; ks < 4; ks++) {
            int kb = ks * 8;
            uint32_t a[2][4];
            #pragma unroll
            for (int mt = 0; mt < 2; mt++) {
                const float* ap = Asm + (wm * 32 + mt * 16 + qr) * 36 + kb + qc;
                a[mt][0] = f2tf(ap[0]);
                a[mt][1] = f2tf(ap[8 * 36]);
                a[mt][2] = f2tf(ap[4]);
                a[mt][3] = f2tf(ap[8 * 36 + 4]);
            }
            #pragma unroll
            for (int nt = 0; nt < 8; nt++) {
                const float* bp = Bsm + (wn * 64 + nt * 8 + qr) * 36 + kb + qc;
                uint32_t b0 = f2tf(bp[0]);
                uint32_t b1 = f2tf(bp[4]);
                mma8(acc[0][nt], a[0], b0, b1);
                mma8(acc[1][nt], a[1], b0, b1);
            }
        }
        __syncthreads();
    }

    const float* Aux = nullptr;
    int ldaux = 0;
    if (MODE == 2) {
        ldaux = buf_ld(auxId);
        Aux = buf_ptr(auxId) + (size_t)e * CAP * ldaux;
    }

    #pragma unroll
    for (int mt = 0; mt < 2; mt++) {
        int r0g = m0 + wm * 32 + mt * 16 + qr;
        #pragma unroll
        for (int nt = 0; nt < 8; nt++) {
            int cg = n0 + wn * 64 + nt * 8 + qc * 2;
            if (cg + 1 >= N && cg >= N) continue;
            #pragma unroll
            for (int half = 0; half < 2; half++) {
                int rr = r0g + half * 8;
                if (rr >= cnt) continue;
                float v0 = acc[mt][nt][half * 2 + 0];
                float v1 = acc[mt][nt][half * 2 + 1];
                if (MODE == 0) {
                    v0 = v0 / (1.f + expf(-v0));
                    v1 = v1 / (1.f + expf(-v1));
                } else if (MODE == 1) {
                    v0 = 1.f / (1.f + expf(-v0));
                    v1 = 1.f / (1.f + expf(-v1));
                } else if (MODE == 2) {
                    v0 *= Aux[(size_t)rr * ldaux + cg];
                    if (cg + 1 < N) v1 *= Aux[(size_t)rr * ldaux + cg + 1];
                }
                float* cp = C + (size_t)rr * ldc + cg;
                if (cg + 1 < N) {
                    float2 st; st.x = v0; st.y = v1;
                    *(float2*)cp = st;
                } else if (cg < N) {
                    cp[0] = v0;
                }
            }
        }
    }
}

// ---------------- kernel 4: per active pair: gates, sinkhorn, h, hn ---------
__global__ void __launch_bounds__(128) k_hn(const float* __restrict__ stream,
                                            const float* __restrict__ b_pre,
                                            const float* __restrict__ b_post,
                                            const float* __restrict__ b_res,
                                            const float* __restrict__ alpha_pre,
                                            const float* __restrict__ alpha_post,
                                            const float* __restrict__ alpha_res,
                                            const float* __restrict__ sw_norm_w)
{
    int row = blockIdx.x;
    int e = blockIdx.y;
    if (row >= g_cnt[e]) return;
    int token = g_tok[e * CAP + row];
    int b = token / TT, t = token % TT;
    int tid = threadIdx.x;

    __shared__ float hpre[NS];
    __shared__ float red2[4];

    if (tid == 0) {
        const float* d = g_dots + (size_t)token * 384 + e * 24;
        size_t slot = (size_t)e * CAP + row;
        float ap = alpha_pre[e], ao = alpha_post[e], ar = alpha_res[e];
        #pragma unroll
        for (int i = 0; i < NS; i++)
            hpre[i] = 1.f / (1.f + expf(-(ap * d[i] + b_pre[e * NS + i])));
        #pragma unroll
        for (int i = 0; i < NS; i++)
            g_Hpost[slot * NS + i] = 2.f / (1.f + expf(-(ao * d[4 + i] + b_post[e * NS + i])));
        float M[16];
        #pragma unroll
        for (int k = 0; k < 16; k++) M[k] = expf(ar * d[8 + k] + b_res[e * 16 + k]);
        for (int it = 0; it < 6; it++) {
            #pragma unroll
            for (int i = 0; i < 4; i++) {
                float rs = M[i*4] + M[i*4+1] + M[i*4+2] + M[i*4+3];
                float ir = 1.f / rs;
                M[i*4] *= ir; M[i*4+1] *= ir; M[i*4+2] *= ir; M[i*4+3] *= ir;
            }
            #pragma unroll
            for (int j = 0; j < 4; j++) {
                float cs = M[j] + M[4+j] + M[8+j] + M[12+j];
                float ic = 1.f / cs;
                M[j] *= ic; M[4+j] *= ic; M[8+j] *= ic; M[12+j] *= ic;
            }
        }
        #pragma unroll
        for (int k = 0; k < 16; k++) g_Hres[slot * 16 + k] = M[k];
    }
    __syncthreads();

    const float* sp0 = stream + ((size_t)b * NS * TT + t) * DD;
    float h0 = hpre[0], h1 = hpre[1], h2 = hpre[2], h3 = hpre[3];
    float hreg[8];
    float hq = 0.f;
    #pragma unroll
    for (int u = 0; u < 8; u++) {
        int dd = tid + u * 128;
        float h = h0 * sp0[dd]
                + h1 * sp0[(size_t)TT * DD + dd]
                + h2 * sp0[2 * (size_t)TT * DD + dd]
                + h3 * sp0[3 * (size_t)TT * DD + dd];
        hreg[u] = h;
        hq += h * h;
    }
    int lane = tid & 31, warp = tid >> 5;
    #pragma unroll
    for (int o = 16; o > 0; o >>= 1) hq += __shfl_down_sync(0xffffffffu, hq, o);
    if (lane == 0) red2[warp] = hq;
    __syncthreads();
    if (tid == 0) red2[0] = rsqrtf((red2[0] + red2[1] + red2[2] + red2[3]) / (float)DD + EPS_F);
    __syncthreads();
    float sh = red2[0];
    const float* snw = sw_norm_w + (size_t)e * DD;
    float* hn = g_HN + ((size_t)e * CAP + row) * DD;
    #pragma unroll
    for (int u = 0; u < 8; u++) {
        int dd = tid + u * 128;
        hn[dd] = hreg[u] * sh * snw[dd];
    }
}

// ---------------- kernel 5: combine res + post ------------------------------
__global__ void __launch_bounds__(128) k_out(const float* __restrict__ stream,
                                             float* __restrict__ outp)
{
    int token = blockIdx.x;
    int b = token / TT, t = token % TT;
    int tid = threadIdx.x;
    const float* sp0 = stream + ((size_t)b * NS * TT + t) * DD;

    float st[4][8], acc[4][8];
    #pragma unroll
    for (int i = 0; i < 4; i++)
        #pragma unroll
        for (int j = 0; j < 8; j++) {
            st[i][j] = sp0[(size_t)i * TT * DD + tid + j * 128];
            acc[i][j] = 0.f;
        }

    for (int e = 0; e < EE; e++) {
        int row = g_row[token * EE + e];
        if (row < 0) continue;
        float g = g_gatev[token * EE + e];
        size_t slot = (size_t)e * CAP + row;
        float Hr[16], Hp[4];
        #pragma unroll
        for (int k = 0; k < 16; k++) Hr[k] = g_Hres[slot * 16 + k];
        #pragma unroll
        for (int i = 0; i < 4; i++) Hp[i] = g_Hpost[slot * 4 + i];
        const float* o = g_OUT + slot * DD;
        #pragma unroll
        for (int j = 0; j < 8; j++) {
            float ov = o[tid + j * 128];
            #pragma unroll
            for (int i = 0; i < 4; i++) {
                float r = Hr[i*4+0] * st[0][j] + Hr[i*4+1] * st[1][j]
                        + Hr[i*4+2] * st[2][j] + Hr[i*4+3] * st[3][j];
                acc[i][j] += g * (r + Hp[i] * ov);
            }
        }
    }
    #pragma unroll
    for (int i = 0; i < 4; i++)
        #pragma unroll
        for (int j = 0; j < 8; j++)
            outp[((size_t)(b * NS + i) * TT + t) * DD + tid + j * 128] = acc[i][j];
}

// ---------------- launch -----------------------------------------------------
extern "C" void kernel_launch(void* const* d_in, const int* in_sizes, int n_in,
                              void* d_out, int out_size)
{
    (void)in_sizes; (void)n_in; (void)out_size;
    const float* stream     = (const float*)d_in[0];
    const float* router_w   = (const float*)d_in[1];
    const float* mhc_norm_w = (const float*)d_in[2];
    const float* phi_pre_w  = (const float*)d_in[3];
    const float* phi_post_w = (const float*)d_in[4];
    const float* phi_res_w  = (const float*)d_in[5];
    const float* b_pre      = (const float*)d_in[6];
    const float* b_post     = (const float*)d_in[7];
    const float* b_res      = (const float*)d_in[8];
    const float* alpha_pre  = (const float*)d_in[9];
    const float* alpha_post = (const float*)d_in[10];
    const float* alpha_res  = (const float*)d_in[11];
    const float* sw_norm_w  = (const float*)d_in[12];
    const float* wd_w       = (const float*)d_in[13];
    const float* wu_w       = (const float*)d_in[14];
    const float* gate_w     = (const float*)d_in[15];
    const float* up_w       = (const float*)d_in[16];
    const float* down_w     = (const float*)d_in[17];

    float* outp = (float*)d_out;
    float* out_gate = outp + (size_t)BB * NS * TT * DD;

    const int SMEM = 73728;
    cudaFuncSetAttribute(k_gemm<0>, cudaFuncAttributeMaxDynamicSharedMemorySize, SMEM);
    cudaFuncSetAttribute(k_gemm<1>, cudaFuncAttributeMaxDynamicSharedMemorySize, SMEM);
    cudaFuncSetAttribute(k_gemm<2>, cudaFuncAttributeMaxDynamicSharedMemorySize, SMEM);
    cudaFuncSetAttribute(k_gemm<3>, cudaFuncAttributeMaxDynamicSharedMemorySize, SMEM);

    float* phiW;
    cudaGetSymbolAddress((void**)&phiW, g_phiW);

    k_zero<<<1, 32>>>();
    k_gate<<<BT, 256>>>(stream, router_w, out_gate);
    k_base<<<BT, 256>>>(stream);
    k_pack<<<(EE * 24 * NDIM) / 1024, 256>>>(mhc_norm_w, phi_pre_w, phi_post_w, phi_res_w);

    // phi logits for all tokens x all experts: dots = base @ phiW^T  (N=384, K=4096)
    k_gemm<3><<<dim3(32, 3, 1), 256, SMEM>>>(ID_BASE, phiW, ID_DOTS, -1, 384, NDIM, NDIM, BT);

    k_hn<<<dim3(CAP, EE), 128>>>(stream, b_pre, b_post, b_res,
                                 alpha_pre, alpha_post, alpha_res, sw_norm_w);

    dim3 gD(32, 8, EE);    // N = 1024
    dim3 gF(32, 13, EE);   // N = 1656

    // T1 = silu(HN @ wd^T)
    k_gemm<0><<<gD, 256, SMEM>>>(ID_HN, wd_w, ID_T1, -1, DD, DD, DD, -1);
    // GS = sigmoid(T1 @ wu^T)
    k_gemm<1><<<gD, 256, SMEM>>>(ID_T1, wu_w, ID_GS, -1, DD, DD, DD, -1);
    // P = silu(HN @ gate_w^T)
    k_gemm<0><<<gF, 256, SMEM>>>(ID_HN, gate_w, ID_P, -1, DFFN, DD, DD, -1);
    // P = (HN @ up_w^T) * P
    k_gemm<2><<<gF, 256, SMEM>>>(ID_HN, up_w, ID_P, ID_P, DFFN, DD, DD, -1);
    // OUT = (P @ down_w^T) * GS   (K padded to 1664, pad cols of P are zero)
    k_gemm<2><<<gD, 256, SMEM>>>(ID_P, down_w, ID_OUT, ID_GS, DD, LDP, DFFN, -1);

    k_out<<<BT, 128>>>(stream, outp);
}